// round 4
// baseline (speedup 1.0000x reference)
#include <cuda_runtime.h>
#include <math.h>

#define N_ITEM 81920
#define E_INT 327680
#define N_TGT 2048
#define NUM_NODE 50000
#define DIM 256
#define KDIM 512
#define ALPHA 0.2f
#define NOUT (NUM_NODE - 1)   // 49999

// ---------------- scratch (device globals; no allocs allowed) ----------------
__device__ float g_hn[(size_t)N_ITEM * DIM];   // gathered item embeddings
__device__ float g_ft[(size_t)N_ITEM * DIM];   // attention-aggregated features
__device__ float g_ex[E_INT];                  // exp(leaky(logit)) per edge
__device__ float g_den[N_ITEM];                // softmax denominators per dst
__device__ float g_sel[(size_t)N_TGT * DIM];   // select accumulator
__device__ float g_qwT[KDIM * DIM];            // q_w transposed to [k][out]

__device__ __forceinline__ void red_add_v4(float* p, float4 v) {
    asm volatile("red.global.add.v4.f32 [%0], {%1,%2,%3,%4};"
                 :: "l"(p), "f"(v.x), "f"(v.y), "f"(v.z), "f"(v.w) : "memory");
}

// ---------------- K0: zero accumulators ----------------
__global__ void k_zero() {
    int t = blockIdx.x * blockDim.x + threadIdx.x;
    int stride = gridDim.x * blockDim.x;
    const int nft = N_ITEM * DIM / 4;
    const int nsel = N_TGT * DIM / 4;
    float4 z = make_float4(0.f, 0.f, 0.f, 0.f);
    for (int i = t; i < nft; i += stride) ((float4*)g_ft)[i] = z;
    for (int i = t; i < nsel; i += stride) ((float4*)g_sel)[i] = z;
    for (int i = t; i < N_ITEM; i += stride) g_den[i] = 0.f;
}

// ---------------- K1: gather h_n = emb[iid] ----------------
__global__ void k_gather(const float* __restrict__ emb, const int* __restrict__ iid) {
    int t = blockIdx.x * blockDim.x + threadIdx.x;   // over N_ITEM * 64 float4
    if (t >= N_ITEM * (DIM / 4)) return;
    int row = t >> 6;
    int c = t & 63;
    ((float4*)g_hn)[t] = ((const float4*)(emb + (size_t)iid[row] * DIM))[c];
}

// ---------------- K1b: transpose q_w -> [k][out] ----------------
__global__ void k_tq(const float* __restrict__ q_w) {
    int t = blockIdx.x * blockDim.x + threadIdx.x;   // over 256*512
    if (t >= DIM * KDIM) return;
    int out = t >> 9;        // /512
    int k = t & 511;
    g_qwT[k * DIM + out] = q_w[t];                   // coalesced read
}

// ---------------- K2: edge logits -> exp, accumulate denominators ----------------
// warp per edge. softmax max-subtraction omitted (mathematically identity; logits
// bounded by ~0.08 so exp is safe).
__global__ void k_edge(const int* __restrict__ i_src, const int* __restrict__ i_dst,
                       const float* __restrict__ p_w) {
    int e = blockIdx.x * 8 + (threadIdx.x >> 5);
    int lane = threadIdx.x & 31;
    int s = i_src[e], d = i_dst[e];
    const float4* sp = (const float4*)(g_hn + (size_t)s * DIM);
    const float4* dp = (const float4*)(g_hn + (size_t)d * DIM);
    const float4* wp = (const float4*)p_w;
    float acc = 0.f;
#pragma unroll
    for (int j = 0; j < 2; j++) {
        int c = lane + 32 * j;
        float4 a = sp[c], b = dp[c], w = __ldg(&wp[c]);
        acc += a.x * b.x * w.x + a.y * b.y * w.y + a.z * b.z * w.z + a.w * b.w * w.w;
    }
#pragma unroll
    for (int o = 16; o; o >>= 1) acc += __shfl_xor_sync(0xffffffffu, acc, o);
    if (lane == 0) {
        float l = acc > 0.f ? acc : ALPHA * acc;
        float ex = expf(l);
        g_ex[e] = ex;
        atomicAdd(&g_den[d], ex);
    }
}

// ---------------- K3: ft[dst] += a * hn[src] ----------------
__global__ void k_scatter(const int* __restrict__ i_src, const int* __restrict__ i_dst) {
    int e = blockIdx.x * 8 + (threadIdx.x >> 5);
    int lane = threadIdx.x & 31;
    int s = i_src[e], d = i_dst[e];
    float a = g_ex[e] / fmaxf(g_den[d], 1e-12f);
    const float4* sp = (const float4*)(g_hn + (size_t)s * DIM);
    float* fp = g_ft + (size_t)d * DIM;
#pragma unroll
    for (int j = 0; j < 2; j++) {
        int c = lane + 32 * j;
        float4 v = sp[c];
        v.x *= a; v.y *= a; v.z *= a; v.w *= a;
        red_add_v4(fp + c * 4, v);
    }
}

// ---------------- K4: fused mid GEMM + tanh + coef dot + select scatter ----------
// block: 256 threads, 64 rows x 256 outputs, K=512. thread = (ty 0..7, tx 0..31),
// computes 8 rows x 8 cols. warp == ty (lane == tx), so the coef reduction over
// the 256 output dims is a butterfly shuffle within the warp.
__global__ __launch_bounds__(256) void k_mid(
    const float* __restrict__ pos_emb, const int* __restrict__ pid,
    const int* __restrict__ agg_src, const int* __restrict__ agg_dst,
    const int* __restrict__ tid_arr, const float* __restrict__ tgt_emb) {
    __shared__ float Ws[32 * 256];      // [kk][col]
    __shared__ float Xs[32][65];        // [kk][row], pad 65 -> conflict-free
    __shared__ int s_src[64], s_pid[64], s_dst[64], s_trow[64];

    int tidx = threadIdx.x;
    int tx = tidx & 31, ty = tidx >> 5;
    int row0 = blockIdx.x * 64;

    if (tidx < 64) {
        int r = row0 + tidx;
        s_src[tidx] = agg_src[r];
        s_pid[tidx] = pid[r];
        int d = agg_dst[r];
        s_dst[tidx] = d;
        s_trow[tidx] = tid_arr[d];
    }
    __syncthreads();

    float acc[8][8];
#pragma unroll
    for (int i = 0; i < 8; i++)
#pragma unroll
        for (int j = 0; j < 8; j++) acc[i][j] = 0.f;

    for (int k0 = 0; k0 < KDIM; k0 += 32) {
        // Ws chunk: 32x256 floats = 2048 float4, 8 per thread (coalesced)
        const float4* wsrc = (const float4*)(g_qwT + k0 * DIM);
#pragma unroll
        for (int it = 0; it < 8; it++) {
            int f = tidx + 256 * it;
            ((float4*)Ws)[f] = wsrc[f];
        }
        // Xs chunk: 64 rows x 32 k, 8 per thread; f = r*32 + kk (coalesced reads)
#pragma unroll
        for (int it = 0; it < 8; it++) {
            int f = tidx + 256 * it;
            int r = f >> 5, kk = f & 31;
            float v;
            if (k0 < DIM)
                v = g_ft[(size_t)s_src[r] * DIM + k0 + kk];
            else
                v = pos_emb[(size_t)s_pid[r] * DIM + (k0 - DIM) + kk];
            Xs[kk][r] = v;
        }
        __syncthreads();
#pragma unroll
        for (int kk = 0; kk < 32; kk++) {
            float4 b0 = *(const float4*)&Ws[kk * 256 + tx * 8];
            float4 b1 = *(const float4*)&Ws[kk * 256 + tx * 8 + 4];
            float a0 = Xs[kk][ty * 8 + 0], a1 = Xs[kk][ty * 8 + 1];
            float a2 = Xs[kk][ty * 8 + 2], a3 = Xs[kk][ty * 8 + 3];
            float a4 = Xs[kk][ty * 8 + 4], a5 = Xs[kk][ty * 8 + 5];
            float a6 = Xs[kk][ty * 8 + 6], a7 = Xs[kk][ty * 8 + 7];
            float av[8] = {a0, a1, a2, a3, a4, a5, a6, a7};
#pragma unroll
            for (int i = 0; i < 8; i++) {
                acc[i][0] += av[i] * b0.x; acc[i][1] += av[i] * b0.y;
                acc[i][2] += av[i] * b0.z; acc[i][3] += av[i] * b0.w;
                acc[i][4] += av[i] * b1.x; acc[i][5] += av[i] * b1.y;
                acc[i][6] += av[i] * b1.z; acc[i][7] += av[i] * b1.w;
            }
        }
        __syncthreads();
    }

    // epilogue: coef[r] = sum_d tanh(e[r,d]) * tgt[trow[r], d]; then
    // select[dst[r]] += coef[r] * ft[src[r]]
#pragma unroll
    for (int i = 0; i < 8; i++) {
        int r = ty * 8 + i;
        const float* tg = tgt_emb + (size_t)s_trow[r] * DIM + tx * 8;
        float p = 0.f;
#pragma unroll
        for (int j = 0; j < 8; j++) p += tanhf(acc[i][j]) * __ldg(&tg[j]);
#pragma unroll
        for (int o = 16; o; o >>= 1) p += __shfl_xor_sync(0xffffffffu, p, o);
        // butterfly: all lanes now hold the full coef
        const float4* fp = (const float4*)(g_ft + (size_t)s_src[r] * DIM);
        float* op = g_sel + (size_t)s_dst[r] * DIM;
#pragma unroll
        for (int j = 0; j < 2; j++) {
            int cc = tx + 32 * j;
            float4 v = fp[cc];
            v.x *= p; v.y *= p; v.z *= p; v.w *= p;
            red_add_v4(op + cc * 4, v);
        }
    }
}

// ---------------- K5: scores = select @ emb[1:]^T ----------------
// 128x128 tile, K=256 in chunks of 32, 256 threads, 8x8 per thread.
__global__ __launch_bounds__(256) void k_scores(const float* __restrict__ emb,
                                                float* __restrict__ out) {
    __shared__ float As[32][132];   // [kk][m]
    __shared__ float Bs[32][132];   // [kk][n]
    int tidx = threadIdx.x;
    int tx = tidx & 15, ty = tidx >> 4;
    int m0 = blockIdx.y * 128;
    int n0 = blockIdx.x * 128;

    float acc[8][8];
#pragma unroll
    for (int i = 0; i < 8; i++)
#pragma unroll
        for (int j = 0; j < 8; j++) acc[i][j] = 0.f;

    for (int k0 = 0; k0 < DIM; k0 += 32) {
#pragma unroll
        for (int it = 0; it < 16; it++) {
            int f = tidx + 256 * it;      // f = m*32 + kk
            int m = f >> 5, kk = f & 31;
            As[kk][m] = g_sel[(size_t)(m0 + m) * DIM + k0 + kk];
        }
#pragma unroll
        for (int it = 0; it < 16; it++) {
            int f = tidx + 256 * it;      // f = n*32 + kk
            int n = f >> 5, kk = f & 31;
            int gn = n0 + n;
            Bs[kk][n] = (gn < NOUT) ? emb[(size_t)(gn + 1) * DIM + k0 + kk] : 0.f;
        }
        __syncthreads();
#pragma unroll
        for (int kk = 0; kk < 32; kk++) {
            float4 a0 = *(const float4*)&As[kk][ty * 8];
            float4 a1 = *(const float4*)&As[kk][ty * 8 + 4];
            float4 b0 = *(const float4*)&Bs[kk][tx * 8];
            float4 b1 = *(const float4*)&Bs[kk][tx * 8 + 4];
            float av[8] = {a0.x, a0.y, a0.z, a0.w, a1.x, a1.y, a1.z, a1.w};
            float bv[8] = {b0.x, b0.y, b0.z, b0.w, b1.x, b1.y, b1.z, b1.w};
#pragma unroll
            for (int i = 0; i < 8; i++)
#pragma unroll
                for (int j = 0; j < 8; j++) acc[i][j] += av[i] * bv[j];
        }
        __syncthreads();
    }

#pragma unroll
    for (int i = 0; i < 8; i++) {
        int m = m0 + ty * 8 + i;
        size_t base = (size_t)m * NOUT;
#pragma unroll
        for (int j = 0; j < 8; j++) {
            int n = n0 + tx * 8 + j;
            if (n < NOUT) out[base + n] = acc[i][j];
        }
    }
}

// ---------------- launch ----------------
extern "C" void kernel_launch(void* const* d_in, const int* in_sizes, int n_in,
                              void* d_out, int out_size) {
    // metadata order: alias_inputs, mask, iid, pid, tid, i_src, i_dst,
    //                 agg_src, agg_dst, emb, pos_emb, tgt_emb, p_w, q_w
    const int* iid = (const int*)d_in[2];
    const int* pid = (const int*)d_in[3];
    const int* tid = (const int*)d_in[4];
    const int* i_src = (const int*)d_in[5];
    const int* i_dst = (const int*)d_in[6];
    const int* agg_src = (const int*)d_in[7];
    const int* agg_dst = (const int*)d_in[8];
    const float* emb = (const float*)d_in[9];
    const float* pos_emb = (const float*)d_in[10];
    const float* tgt_emb = (const float*)d_in[11];
    const float* p_w = (const float*)d_in[12];
    const float* q_w = (const float*)d_in[13];
    float* out = (float*)d_out;

    k_zero<<<2048, 256>>>();
    k_gather<<<(N_ITEM * (DIM / 4) + 255) / 256, 256>>>(emb, iid);
    k_tq<<<(DIM * KDIM + 255) / 256, 256>>>(q_w);
    k_edge<<<E_INT / 8, 256>>>(i_src, i_dst, p_w);
    k_scatter<<<E_INT / 8, 256>>>(i_src, i_dst);
    k_mid<<<N_ITEM / 64, 256>>>(pos_emb, pid, agg_src, agg_dst, tid, tgt_emb);
    dim3 g5((NOUT + 127) / 128, (N_TGT + 127) / 128);
    k_scores<<<g5, 256>>>(emb, out);
}

// round 9
// speedup vs baseline: 2.6178x; 2.6178x over previous
#include <cuda_runtime.h>
#include <math.h>
#include <stdint.h>

#define N_ITEM 81920
#define E_INT 327680
#define N_TGT 2048
#define NUM_NODE 50000
#define DIM 256
#define KDIM 512
#define ALPHA 0.2f
#define NOUT 49999

// ---------------- scratch (device globals; no allocs allowed) ----------------
__device__ float g_hn[(size_t)N_ITEM * DIM];    // gathered item embeddings
__device__ float g_ft[(size_t)N_ITEM * DIM];    // attention-aggregated (full fp32)
__device__ float g_ex[E_INT];                   // exp(leaky(logit)) per edge
__device__ float g_den[N_ITEM];                 // softmax denominators
__device__ float g_sel[(size_t)N_TGT * DIM];    // select accumulator (fp32)
// tf32-rounded copies for mma.sync consumption
__device__ float g_embr[(size_t)NUM_NODE * DIM];
__device__ float g_ftr[(size_t)N_ITEM * DIM];
__device__ float g_selr[(size_t)N_TGT * DIM];
__device__ float g_qwr[DIM * KDIM];
__device__ float g_posr[200 * DIM];

__device__ __forceinline__ void red_add_v4(float* p, float4 v) {
    asm volatile("red.global.add.v4.f32 [%0], {%1,%2,%3,%4};"
                 :: "l"(p), "f"(v.x), "f"(v.y), "f"(v.z), "f"(v.w) : "memory");
}
__device__ __forceinline__ uint32_t s2u(const void* p) {
    uint32_t a;
    asm("{ .reg .u64 t; cvta.to.shared.u64 t, %1; cvt.u32.u64 %0, t; }"
        : "=r"(a) : "l"(p));
    return a;
}
__device__ __forceinline__ float tf32r(float x) {
    float r; asm("cvt.rna.tf32.f32 %0, %1;" : "=f"(r) : "f"(x)); return r;
}
__device__ __forceinline__ void f4tf32(float4& v) {
    v.x = tf32r(v.x); v.y = tf32r(v.y); v.z = tf32r(v.z); v.w = tf32r(v.w);
}
__device__ __forceinline__ void cp16(uint32_t s, const void* g) {
    asm volatile("cp.async.cg.shared.global [%0], [%1], 16;"
                 :: "r"(s), "l"(g) : "memory");
}
__device__ __forceinline__ void cp16z(uint32_t s, const void* g, uint32_t sz) {
    asm volatile("cp.async.cg.shared.global [%0], [%1], 16, %2;"
                 :: "r"(s), "l"(g), "r"(sz) : "memory");
}
#define CP_COMMIT() asm volatile("cp.async.commit_group;" ::: "memory")
#define CP_WAIT1() asm volatile("cp.async.wait_group 1;" ::: "memory")
#define CP_WAIT0() asm volatile("cp.async.wait_group 0;" ::: "memory")

__device__ __forceinline__ void mma_tf32(float* d, const uint32_t* a, const uint32_t* b) {
    asm volatile(
        "mma.sync.aligned.m16n8k8.row.col.f32.tf32.tf32.f32 "
        "{%0,%1,%2,%3}, {%4,%5,%6,%7}, {%8,%9}, {%0,%1,%2,%3};"
        : "+f"(d[0]), "+f"(d[1]), "+f"(d[2]), "+f"(d[3])
        : "r"(a[0]), "r"(a[1]), "r"(a[2]), "r"(a[3]), "r"(b[0]), "r"(b[1]));
}

// ---------------- K0: zero accumulators ----------------
__global__ void k_zero() {
    int t = blockIdx.x * blockDim.x + threadIdx.x;
    int stride = gridDim.x * blockDim.x;
    const int nft = N_ITEM * DIM / 4;
    const int nsel = N_TGT * DIM / 4;
    float4 z = make_float4(0.f, 0.f, 0.f, 0.f);
    for (int i = t; i < nft; i += stride) ((float4*)g_ft)[i] = z;
    for (int i = t; i < nsel; i += stride) ((float4*)g_sel)[i] = z;
    for (int i = t; i < N_ITEM; i += stride) g_den[i] = 0.f;
}

// ---------------- K1: gather h_n = emb[iid] ----------------
__global__ void k_gather(const float* __restrict__ emb, const int* __restrict__ iid) {
    int t = blockIdx.x * blockDim.x + threadIdx.x;
    if (t >= N_ITEM * (DIM / 4)) return;
    int row = t >> 6;
    int c = t & 63;
    ((float4*)g_hn)[t] = ((const float4*)(emb + (size_t)iid[row] * DIM))[c];
}

// ---------------- rounding prep kernels ----------------
template <int DST>
__global__ void k_round_in(const float4* __restrict__ src, int n4) {
    int i = blockIdx.x * blockDim.x + threadIdx.x;
    if (i >= n4) return;
    float4 v = src[i];
    f4tf32(v);
    float4* d = (DST == 0) ? (float4*)g_embr : (DST == 1) ? (float4*)g_qwr
                                                          : (float4*)g_posr;
    d[i] = v;
}
__global__ void k_round_ft() {
    int i = blockIdx.x * blockDim.x + threadIdx.x;
    if (i >= N_ITEM * (DIM / 4)) return;
    float4 v = ((const float4*)g_ft)[i];
    f4tf32(v);
    ((float4*)g_ftr)[i] = v;
}
__global__ void k_round_sel() {
    int i = blockIdx.x * blockDim.x + threadIdx.x;
    if (i >= N_TGT * (DIM / 4)) return;
    float4 v = ((const float4*)g_sel)[i];
    f4tf32(v);
    ((float4*)g_selr)[i] = v;
}

// ---------------- K2: edge logits -> exp, denominators ----------------
__global__ void k_edge(const int* __restrict__ i_src, const int* __restrict__ i_dst,
                       const float* __restrict__ p_w) {
    int e = blockIdx.x * 8 + (threadIdx.x >> 5);
    int lane = threadIdx.x & 31;
    int s = i_src[e], d = i_dst[e];
    const float4* sp = (const float4*)(g_hn + (size_t)s * DIM);
    const float4* dp = (const float4*)(g_hn + (size_t)d * DIM);
    const float4* wp = (const float4*)p_w;
    float acc = 0.f;
#pragma unroll
    for (int j = 0; j < 2; j++) {
        int c = lane + 32 * j;
        float4 a = sp[c], b = dp[c], w = __ldg(&wp[c]);
        acc += a.x * b.x * w.x + a.y * b.y * w.y + a.z * b.z * w.z + a.w * b.w * w.w;
    }
#pragma unroll
    for (int o = 16; o; o >>= 1) acc += __shfl_xor_sync(0xffffffffu, acc, o);
    if (lane == 0) {
        float l = acc > 0.f ? acc : ALPHA * acc;
        float ex = expf(l);
        g_ex[e] = ex;
        atomicAdd(&g_den[d], ex);
    }
}

// ---------------- K3: ft[dst] += a * hn[src] ----------------
__global__ void k_scatter(const int* __restrict__ i_src, const int* __restrict__ i_dst) {
    int e = blockIdx.x * 8 + (threadIdx.x >> 5);
    int lane = threadIdx.x & 31;
    int s = i_src[e], d = i_dst[e];
    float a = g_ex[e] / fmaxf(g_den[d], 1e-12f);
    const float4* sp = (const float4*)(g_hn + (size_t)s * DIM);
    float* fp = g_ft + (size_t)d * DIM;
#pragma unroll
    for (int j = 0; j < 2; j++) {
        int c = lane + 32 * j;
        float4 v = sp[c];
        v.x *= a; v.y *= a; v.z *= a; v.w *= a;
        red_add_v4(fp + c * 4, v);
    }
}

// ---------------- K4: mid GEMM (mma.sync tf32) + tanh/coef/scatter ----------
// C[64,256] per CTA = X[64,512] @ q_w^T. 8 warps: wm=wid&1 (32 rows), wn=wid>>1
// (64 cols). Warp tile 32x64 = 2 m16-tiles x 8 n8-tiles, m16n8k8.
__global__ __launch_bounds__(256) void k_mid_mma(
    const int* __restrict__ pid, const int* __restrict__ agg_src,
    const int* __restrict__ agg_dst, const int* __restrict__ tid_arr,
    const float* __restrict__ tgt_emb) {
    extern __shared__ float sm[];
    float* Abuf[2] = {sm, sm + 2304};                 // 64*36 floats each
    float* Bbuf[2] = {sm + 4608, sm + 4608 + 9216};   // 256*36 floats each
    __shared__ int s_src[64], s_pid[64], s_dst[64], s_trow[64];
    __shared__ float s_coef[64];

    int tid = threadIdx.x, lane = tid & 31, wid = tid >> 5;
    int gid = lane >> 2, tig = lane & 3;
    int wm = wid & 1, wn = wid >> 1;
    int m0 = blockIdx.x * 64;

    if (tid < 64) {
        int r = m0 + tid;
        s_src[tid] = agg_src[r];
        s_pid[tid] = pid[r];
        int d = agg_dst[r];
        s_dst[tid] = d;
        s_trow[tid] = tid_arr[d];
        s_coef[tid] = 0.f;
    }
    __syncthreads();

    auto load_chunk = [&](int c, int b) {
        int k0 = c * 32;
#pragma unroll
        for (int it = 0; it < 2; it++) {
            int f = tid + 256 * it;
            int row = f >> 3, c4 = f & 7;
            const float* src = (k0 < DIM)
                ? g_ftr + (size_t)s_src[row] * DIM + k0 + c4 * 4
                : g_posr + (size_t)s_pid[row] * DIM + (k0 - DIM) + c4 * 4;
            cp16(s2u(&Abuf[b][row * 36 + c4 * 4]), src);
        }
#pragma unroll
        for (int it = 0; it < 8; it++) {
            int f = tid + 256 * it;
            int row = f >> 3, c4 = f & 7;
            cp16(s2u(&Bbuf[b][row * 36 + c4 * 4]),
                 g_qwr + (size_t)row * KDIM + k0 + c4 * 4);
        }
        CP_COMMIT();
    };

    float acc[2][8][4];
#pragma unroll
    for (int i = 0; i < 2; i++)
#pragma unroll
        for (int j = 0; j < 8; j++)
#pragma unroll
            for (int q = 0; q < 4; q++) acc[i][j][q] = 0.f;

    load_chunk(0, 0);
    for (int c = 0; c < 16; c++) {
        int b = c & 1;
        if (c + 1 < 16) { load_chunk(c + 1, b ^ 1); CP_WAIT1(); }
        else CP_WAIT0();
        __syncthreads();
        const float* A = Abuf[b];
        const float* B = Bbuf[b];
#pragma unroll
        for (int k8 = 0; k8 < 4; k8++) {
            int kk = k8 * 8 + tig;
            uint32_t aF[2][4];
#pragma unroll
            for (int mt = 0; mt < 2; mt++) {
                int r0 = wm * 32 + mt * 16 + gid;
                aF[mt][0] = __float_as_uint(A[r0 * 36 + kk]);
                aF[mt][1] = __float_as_uint(A[(r0 + 8) * 36 + kk]);
                aF[mt][2] = __float_as_uint(A[r0 * 36 + kk + 4]);
                aF[mt][3] = __float_as_uint(A[(r0 + 8) * 36 + kk + 4]);
            }
            uint32_t bF[8][2];
#pragma unroll
            for (int nt = 0; nt < 8; nt++) {
                int n = wn * 64 + nt * 8 + gid;
                bF[nt][0] = __float_as_uint(B[n * 36 + kk]);
                bF[nt][1] = __float_as_uint(B[n * 36 + kk + 4]);
            }
#pragma unroll
            for (int mt = 0; mt < 2; mt++)
#pragma unroll
                for (int nt = 0; nt < 8; nt++)
                    mma_tf32(acc[mt][nt], aF[mt], bF[nt]);
        }
        __syncthreads();
    }

    // coef partials: rows (wm*32+mt*16+gid, +8); cols (wn*64+nt*8+tig*2, +1)
    float p[4] = {0.f, 0.f, 0.f, 0.f};
#pragma unroll
    for (int mt = 0; mt < 2; mt++) {
        int r0 = wm * 32 + mt * 16 + gid;
        const float* tg0 = tgt_emb + (size_t)s_trow[r0] * DIM;
        const float* tg1 = tgt_emb + (size_t)s_trow[r0 + 8] * DIM;
#pragma unroll
        for (int nt = 0; nt < 8; nt++) {
            int n = wn * 64 + nt * 8 + tig * 2;
            p[mt * 2 + 0] += tanhf(acc[mt][nt][0]) * __ldg(&tg0[n])
                           + tanhf(acc[mt][nt][1]) * __ldg(&tg0[n + 1]);
            p[mt * 2 + 1] += tanhf(acc[mt][nt][2]) * __ldg(&tg1[n])
                           + tanhf(acc[mt][nt][3]) * __ldg(&tg1[n + 1]);
        }
    }
#pragma unroll
    for (int i = 0; i < 4; i++) {
        p[i] += __shfl_xor_sync(0xffffffffu, p[i], 1);
        p[i] += __shfl_xor_sync(0xffffffffu, p[i], 2);
    }
    if (tig == 0) {
        atomicAdd(&s_coef[wm * 32 + gid], p[0]);
        atomicAdd(&s_coef[wm * 32 + gid + 8], p[1]);
        atomicAdd(&s_coef[wm * 32 + 16 + gid], p[2]);
        atomicAdd(&s_coef[wm * 32 + 16 + gid + 8], p[3]);
    }
    __syncthreads();

    // scatter: select[dst] += coef * ft[src] (full-precision ft)
#pragma unroll
    for (int i = 0; i < 8; i++) {
        int rl = wid * 8 + i;
        float cf = s_coef[rl];
        const float4* fp = (const float4*)(g_ft + (size_t)s_src[rl] * DIM);
        float* op = g_sel + (size_t)s_dst[rl] * DIM;
#pragma unroll
        for (int j = 0; j < 2; j++) {
            int cc = lane + 32 * j;
            float4 v = fp[cc];
            v.x *= cf; v.y *= cf; v.z *= cf; v.w *= cf;
            red_add_v4(op + cc * 4, v);
        }
    }
}

// ---------------- K5: scores = selr @ embr[1:]^T (mma.sync tf32) ------------
// 128x128 block tile, 8 warps: wm=wid&3 (32 rows), wn=wid>>2 (64 cols).
__global__ __launch_bounds__(256) void k_scores_mma(float* __restrict__ out) {
    extern __shared__ float sm[];
    float* Abuf[2] = {sm, sm + 4608};                 // 128*36 floats each
    float* Bbuf[2] = {sm + 9216, sm + 9216 + 4608};
    int tid = threadIdx.x, lane = tid & 31, wid = tid >> 5;
    int gid = lane >> 2, tig = lane & 3;
    int wm = wid & 3, wn = wid >> 2;
    int n0 = blockIdx.x * 128, m0 = blockIdx.y * 128;

    auto load_chunk = [&](int c, int b) {
        int k0 = c * 32;
#pragma unroll
        for (int it = 0; it < 4; it++) {
            int f = tid + 256 * it;
            int row = f >> 3, c4 = f & 7;
            cp16(s2u(&Abuf[b][row * 36 + c4 * 4]),
                 g_selr + (size_t)(m0 + row) * DIM + k0 + c4 * 4);
        }
#pragma unroll
        for (int it = 0; it < 4; it++) {
            int f = tid + 256 * it;
            int row = f >> 3, c4 = f & 7;
            int gn = n0 + row;
            uint32_t ok = (gn < NOUT) ? 16u : 0u;
            const float* src = g_embr + (size_t)((gn < NOUT) ? gn + 1 : 0) * DIM
                             + k0 + c4 * 4;
            cp16z(s2u(&Bbuf[b][row * 36 + c4 * 4]), src, ok);
        }
        CP_COMMIT();
    };

    float acc[2][8][4];
#pragma unroll
    for (int i = 0; i < 2; i++)
#pragma unroll
        for (int j = 0; j < 8; j++)
#pragma unroll
            for (int q = 0; q < 4; q++) acc[i][j][q] = 0.f;

    load_chunk(0, 0);
    for (int c = 0; c < 8; c++) {
        int b = c & 1;
        if (c + 1 < 8) { load_chunk(c + 1, b ^ 1); CP_WAIT1(); }
        else CP_WAIT0();
        __syncthreads();
        const float* A = Abuf[b];
        const float* B = Bbuf[b];
#pragma unroll
        for (int k8 = 0; k8 < 4; k8++) {
            int kk = k8 * 8 + tig;
            uint32_t aF[2][4];
#pragma unroll
            for (int mt = 0; mt < 2; mt++) {
                int r0 = wm * 32 + mt * 16 + gid;
                aF[mt][0] = __float_as_uint(A[r0 * 36 + kk]);
                aF[mt][1] = __float_as_uint(A[(r0 + 8) * 36 + kk]);
                aF[mt][2] = __float_as_uint(A[r0 * 36 + kk + 4]);
                aF[mt][3] = __float_as_uint(A[(r0 + 8) * 36 + kk + 4]);
            }
            uint32_t bF[8][2];
#pragma unroll
            for (int nt = 0; nt < 8; nt++) {
                int n = wn * 64 + nt * 8 + gid;
                bF[nt][0] = __float_as_uint(B[n * 36 + kk]);
                bF[nt][1] = __float_as_uint(B[n * 36 + kk + 4]);
            }
#pragma unroll
            for (int mt = 0; mt < 2; mt++)
#pragma unroll
                for (int nt = 0; nt < 8; nt++)
                    mma_tf32(acc[mt][nt], aF[mt], bF[nt]);
        }
        __syncthreads();
    }

    // epilogue: direct STG from fragments
#pragma unroll
    for (int mt = 0; mt < 2; mt++) {
        int r0 = m0 + wm * 32 + mt * 16 + gid;
#pragma unroll
        for (int nt = 0; nt < 8; nt++) {
            int n = n0 + wn * 64 + nt * 8 + tig * 2;
            if (n < NOUT) {
                out[(size_t)r0 * NOUT + n] = acc[mt][nt][0];
                out[(size_t)(r0 + 8) * NOUT + n] = acc[mt][nt][2];
                if (n + 1 < NOUT) {
                    out[(size_t)r0 * NOUT + n + 1] = acc[mt][nt][1];
                    out[(size_t)(r0 + 8) * NOUT + n + 1] = acc[mt][nt][3];
                }
            }
        }
    }
}

// ---------------- launch ----------------
extern "C" void kernel_launch(void* const* d_in, const int* in_sizes, int n_in,
                              void* d_out, int out_size) {
    const int* iid = (const int*)d_in[2];
    const int* pid = (const int*)d_in[3];
    const int* tid = (const int*)d_in[4];
    const int* i_src = (const int*)d_in[5];
    const int* i_dst = (const int*)d_in[6];
    const int* agg_src = (const int*)d_in[7];
    const int* agg_dst = (const int*)d_in[8];
    const float* emb = (const float*)d_in[9];
    const float* pos_emb = (const float*)d_in[10];
    const float* tgt_emb = (const float*)d_in[11];
    const float* p_w = (const float*)d_in[12];
    const float* q_w = (const float*)d_in[13];
    float* out = (float*)d_out;

    static bool attr_set = false;
    (void)attr_set;
    cudaFuncSetAttribute(k_mid_mma, cudaFuncAttributeMaxDynamicSharedMemorySize,
                         92160);
    cudaFuncSetAttribute(k_scores_mma, cudaFuncAttributeMaxDynamicSharedMemorySize,
                         73728);

    k_zero<<<2048, 256>>>();
    k_gather<<<(N_ITEM * (DIM / 4) + 255) / 256, 256>>>(emb, iid);
    k_round_in<0><<<(NUM_NODE * (DIM / 4) + 255) / 256, 256>>>(
        (const float4*)emb, NUM_NODE * (DIM / 4));
    k_round_in<1><<<(DIM * KDIM / 4 + 255) / 256, 256>>>(
        (const float4*)q_w, DIM * KDIM / 4);
    k_round_in<2><<<(200 * (DIM / 4) + 255) / 256, 256>>>(
        (const float4*)pos_emb, 200 * (DIM / 4));
    k_edge<<<E_INT / 8, 256>>>(i_src, i_dst, p_w);
    k_scatter<<<E_INT / 8, 256>>>(i_src, i_dst);
    k_round_ft<<<(N_ITEM * (DIM / 4) + 255) / 256, 256>>>();
    k_mid_mma<<<N_ITEM / 64, 256, 92160>>>(pid, agg_src, agg_dst, tid, tgt_emb);
    k_round_sel<<<(N_TGT * (DIM / 4) + 255) / 256, 256>>>();
    dim3 g5((NOUT + 127) / 128, N_TGT / 128);
    k_scores_mma<<<g5, 256, 73728>>>(out);
}